// round 8
// baseline (speedup 1.0000x reference)
#include <cuda_runtime.h>
#include <cstdint>

typedef unsigned long long ull;

__constant__ float cCC[6]  = {0.f, 0.2f, 0.3f, 0.8f, (float)(8.0/9.0), 1.0f};
__constant__ float cBWv[6] = {(float)(35.0/384.0), 0.f, (float)(500.0/1113.0),
                              (float)(125.0/192.0), (float)(-2187.0/6784.0),
                              (float)(11.0/84.0)};

// ---- smem layout (float offsets) ----
#define oXs  0        /* [g:2][s2:2][128] = 512 */
#define oA   512      /* [s2:2][128] = 256 (shared across groups, phase-disjoint) */
#define oHP  768      /* [kq:4][s2:2][128] = 1024 (shared, phase-disjoint) */
#define oPb  1792     /* [g:2][p:2][rank:4][c:128 ull] = 4096 */
#define oStg 5888     /* [g:2][p:2][c:128 ull] = 1024 */
#define oScr 6912     /* 32 */
#define oTx  6944     /* 4 */
#define oLp  6948     /* 4 */
#define SMF  6952

__device__ __forceinline__ ull pk(float w) {
  ull r; asm("mov.b64 %0, {%1, %2};" : "=l"(r) : "f"(w), "f"(w)); return r;
}
__device__ __forceinline__ ull mk2(float a, float b) {
  ull r; asm("mov.b64 %0, {%1, %2};" : "=l"(r) : "f"(a), "f"(b)); return r;
}
__device__ __forceinline__ float lo32(ull v) { return __uint_as_float((unsigned)v); }
__device__ __forceinline__ float hi32(ull v) { return __uint_as_float((unsigned)(v >> 32)); }
__device__ __forceinline__ ull f2fma(ull a, ull b, ull c) {
  ull d; asm("fma.rn.f32x2 %0,%1,%2,%3;" : "=l"(d) : "l"(a), "l"(b), "l"(c)); return d;
}
__device__ __forceinline__ ull f2add(ull a, ull b) {
  ull d; asm("add.rn.f32x2 %0,%1,%2;" : "=l"(d) : "l"(a), "l"(b)); return d;
}
__device__ __forceinline__ ull f2mul(ull a, ull b) {
  ull d; asm("mul.rn.f32x2 %0,%1,%2;" : "=l"(d) : "l"(a), "l"(b)); return d;
}
__device__ __forceinline__ float wsum(float v) {
#pragma unroll
  for (int o = 16; o > 0; o >>= 1) v += __shfl_xor_sync(0xffffffffu, v, o);
  return v;
}
__device__ __forceinline__ uint32_t smem_u32(const void* p) {
  uint32_t a;
  asm("{.reg .u64 t; cvta.to.shared.u64 t, %1; cvt.u32.u64 %0, t;}" : "=r"(a) : "l"(p));
  return a;
}
__device__ __forceinline__ uint32_t mapa_u32(uint32_t addr, uint32_t rank) {
  uint32_t ra; asm("mapa.shared::cluster.u32 %0, %1, %2;" : "=r"(ra) : "r"(addr), "r"(rank));
  return ra;
}
__device__ __forceinline__ float ldcf(uint32_t addr, uint32_t rank) {
  uint32_t ra = mapa_u32(addr, rank);
  float v; asm volatile("ld.shared::cluster.f32 %0, [%1];" : "=f"(v) : "r"(ra)); return v;
}
__device__ __forceinline__ void csync() {
  asm volatile("barrier.cluster.arrive.aligned;" ::: "memory");
  asm volatile("barrier.cluster.wait.aligned;" ::: "memory");
}
__device__ __forceinline__ void mbar_init(uint32_t mb, unsigned cnt) {
  asm volatile("mbarrier.init.shared::cta.b64 [%0], %1;" :: "r"(mb), "r"(cnt) : "memory");
}
__device__ __forceinline__ void mbar_arm(uint32_t mb, unsigned tx) {
  asm volatile("mbarrier.arrive.expect_tx.shared::cta.b64 _, [%0], %1;"
               :: "r"(mb), "r"(tx) : "memory");
}
__device__ __forceinline__ void bulk_copy256(uint32_t dst_cluster, uint32_t src_cta,
                                             uint32_t rmb_cluster) {
  asm volatile(
      "cp.async.bulk.shared::cluster.shared::cta.mbarrier::complete_tx::bytes "
      "[%0], [%1], 256, [%2];"
      :: "r"(dst_cluster), "r"(src_cta), "r"(rmb_cluster) : "memory");
}
__device__ __forceinline__ void waitp(uint32_t mb, unsigned ph) {
  unsigned done;
  asm volatile(
      "{\n\t.reg .pred p;\n\t"
      "mbarrier.try_wait.parity.acquire.cluster.shared::cta.b64 p, [%1], %2;\n\t"
      "selp.u32 %0,1,0,p;\n\t}"
      : "=r"(done) : "r"(mb), "r"(ph) : "memory");
  while (!done) {
    asm volatile(
        "{\n\t.reg .pred p;\n\t"
        "mbarrier.try_wait.parity.acquire.cluster.shared::cta.b64 p, [%1], %2, 0x989680;\n\t"
        "selp.u32 %0,1,0,p;\n\t}"
        : "=r"(done) : "r"(mb), "r"(ph) : "memory");
  }
}
__device__ __forceinline__ float ftanh(float x) {
  float e = __expf(2.f * x);
  return 1.f - __fdividef(2.f, e + 1.f);
}

// GEMM half: thread (cq = t&63, kq = t>>6) computes output cols {cq, cq+64}
// for the 2 samples of the active group over k in [32kq, 32kq+32). src:
// [s2:2][128] rows; dst: [kq][s2][128].
__device__ __forceinline__ void gemm_h(const ull (&w)[2][16],
                                       const float* __restrict__ src,
                                       float* __restrict__ dst, int kq, int cq) {
  ull a00 = 0, a01 = 0, a10 = 0, a11 = 0;
  const float* s0 = src + (kq << 5);
#pragma unroll
  for (int i = 0; i < 8; ++i) {             // 4 k per iter (2 k-pairs)
    ulonglong2 xa = *(const ulonglong2*)(s0 + (i << 2));         // sample 0
    ulonglong2 xb = *(const ulonglong2*)(s0 + 128 + (i << 2));   // sample 1
    ull w0a = w[0][2 * i], w0b = w[0][2 * i + 1];
    ull w1a = w[1][2 * i], w1b = w[1][2 * i + 1];
    a00 = f2fma(w0a, xa.x, a00); a00 = f2fma(w0b, xa.y, a00);
    a01 = f2fma(w0a, xb.x, a01); a01 = f2fma(w0b, xb.y, a01);
    a10 = f2fma(w1a, xa.x, a10); a10 = f2fma(w1b, xa.y, a10);
    a11 = f2fma(w1a, xb.x, a11); a11 = f2fma(w1b, xb.y, a11);
  }
  float* d0 = dst + (kq << 8) + cq;
  d0[0]         = lo32(a00) + hi32(a00);
  d0[128]       = lo32(a01) + hi32(a01);
  d0[64]        = lo32(a10) + hi32(a10);
  d0[128 + 64]  = lo32(a11) + hi32(a11);
}

__global__ void __launch_bounds__(256, 1) __cluster_dims__(4, 1, 1)
vino_kernel(const float* __restrict__ x0g, const float* __restrict__ W1g,
            const float* __restrict__ b1g, const float* __restrict__ u1g,
            const float* __restrict__ W2g, const float* __restrict__ b2g,
            const int* __restrict__ nsp, float* __restrict__ out, int B) {
  __shared__ __align__(16) float sm[SMF];
  __shared__ __align__(8) unsigned long long smbar[4];   // [g][p]
  const int t = threadIdx.x;
  const int w = t >> 5, lane = t & 31;
  const int cq = t & 63, kq = t >> 6;       // GEMM tiling
  const int c = t & 127, myg = t >> 7;      // my epilogue element: group myg, col c
  const int wg = w & 3;                     // warp index within my group
  uint32_t rank; asm("mov.u32 %0, %%cluster_ctarank;" : "=r"(rank));
  const int hbase = (int)rank << 7;
  const int sb = (blockIdx.x >> 2) << 2;

  // ---- persistent k-pair-packed weight registers ----
  ull w1p[2][16], w2p[2][16];
#pragma unroll
  for (int i = 0; i < 16; ++i) {
    const int kk = (kq << 5) + 2 * i;
    w1p[0][i] = mk2(W1g[kk * 512 + hbase + cq],      W1g[(kk + 1) * 512 + hbase + cq]);
    w1p[1][i] = mk2(W1g[kk * 512 + hbase + cq + 64], W1g[(kk + 1) * 512 + hbase + cq + 64]);
    w2p[0][i] = mk2(W2g[(hbase + kk) * 128 + cq],      W2g[(hbase + kk + 1) * 128 + cq]);
    w2p[1][i] = mk2(W2g[(hbase + kk) * 128 + cq + 64], W2g[(hbase + kk + 1) * 128 + cq + 64]);
  }

  // ---- per-thread constants ----
  const float b1r = b1g[hbase + c];
  const float u1r = u1g[hbase + c];
  const ull b2p = pk(b2g[c]);
  float mr = 0.f;
#pragma unroll 4
  for (int i = 0; i < 128; ++i)
    mr = fmaf(W1g[i * 512 + hbase + c], W2g[(hbase + c) * 128 + i], mr);

  // ---- state: samples (2*myg, 2*myg+1), col c, pair-packed ----
  ull y = mk2(x0g[(sb + 2 * myg) * 128 + c], x0g[(sb + 2 * myg + 1) * 128 + c]);
  ull xs = y;
  sm[oXs + myg * 256 + c]       = lo32(xs);
  sm[oXs + myg * 256 + 128 + c] = hi32(xs);

  // ---- mbarriers + bulk-copy addresses (p=0 base; p adds fixed offsets) ----
  const uint32_t sbase = smem_u32(sm);
  const uint32_t mb0 = smem_u32(&smbar[0]);
  if (t == 0) {
#pragma unroll
    for (int m = 0; m < 4; ++m) { mbar_init(mb0 + m * 8, 1); mbar_arm(mb0 + m * 8, 4096u); }
  }
  const uint32_t mybmb = mb0 + (uint32_t)myg * 16;   // my group's (p=0) mbar
  const uint32_t stg0 = sbase + (uint32_t)(oStg + myg * 512 + wg * 64) * 4u;
  uint32_t dstb[4], rmb[4];
  {
    const uint32_t doff = sbase + (uint32_t)(oPb + myg * 2048 + (int)rank * 256 + wg * 64) * 4u;
#pragma unroll
    for (uint32_t r = 0; r < 4; ++r) {
      dstb[r] = mapa_u32(doff, r);
      rmb[r]  = mapa_u32(mybmb, r);
    }
  }

  // ---- log p(x0) ----
  {
    float q0 = lo32(y), q1 = hi32(y);
    float ss0 = wsum(q0 * q0), ss1 = wsum(q1 * q1);
    if (lane == 0) { sm[oScr + w * 2] = ss0; sm[oScr + w * 2 + 1] = ss1; }
  }
  __syncthreads();
  if (t < 4) {
    const int gg = t >> 1, sp = t & 1;
    float ss = 0.f;
#pragma unroll
    for (int q = 0; q < 4; ++q) ss += sm[oScr + ((4 * gg + q) << 1) + sp];
    sm[oLp + t] = -0.5f * ss - 117.6241322501981f;  // 64*log(2*pi)
  }
  csync();  // mbar arming + smem init visible cluster-wide

  const int ns = *nsp;
  const float dt = 1.0f / (float)ns;
  ull ks0 = 0, ks1 = 0, ks2 = 0, ks3 = 0, ks4 = 0;
  ull acc_tr = 0, acc_dot = 0;
  unsigned php0 = 0, php1 = 0;   // my group's buffer-parity phases
  const int nhs = 2 * 6 * ns;    // 192 half-stages

#pragma unroll 1
  for (int hs = 0; hs < nhs; ++hs) {
    const int g = hs & 1;
    const int idx = hs >> 1;             // group-g stage counter
    const int stage = idx % 6;
    const bool mine = (myg == g);

    // ---- wait + assemble previous stage's k (my group only) ----
    if (hs >= 2 && mine) {
      const int pidx = idx - 1;
      const int pstage = pidx % 6;
      const int p = pidx & 1;
      const float pcoef = dt * cBWv[pstage];
      {
        const uint32_t lmb = mybmb + ((uint32_t)p << 3);
        unsigned ph = p ? php1 : php0;
        waitp(lmb, ph);
        if (p) php1 ^= 1; else php0 ^= 1;
        if (c == 0) mbar_arm(lmb, 4096u);
      }
      const float* pb = sm + oPb + myg * 2048 + (p << 10);
      const int e2g = c << 1;
      ull kacc = f2add(f2add(*(const ull*)(pb + e2g),       *(const ull*)(pb + 256 + e2g)),
                       f2add(*(const ull*)(pb + 512 + e2g), *(const ull*)(pb + 768 + e2g)));
      kacc = f2add(kacc, b2p);
      acc_dot = f2fma(f2mul(xs, kacc), pk(pcoef), acc_dot);
      ull acc;
      switch (pstage) {
        case 0:
          ks0 = kacc;
          acc = f2mul(pk(0.2f), ks0);
          xs = f2fma(pk(dt), acc, y);
          break;
        case 1:
          ks1 = kacc;
          acc = f2mul(pk(0.075f), ks0);
          acc = f2fma(pk(0.225f), ks1, acc);
          xs = f2fma(pk(dt), acc, y);
          break;
        case 2:
          ks2 = kacc;
          acc = f2mul(pk((float)(44.0 / 45.0)), ks0);
          acc = f2fma(pk((float)(-56.0 / 15.0)), ks1, acc);
          acc = f2fma(pk((float)(32.0 / 9.0)), ks2, acc);
          xs = f2fma(pk(dt), acc, y);
          break;
        case 3:
          ks3 = kacc;
          acc = f2mul(pk((float)(19372.0 / 6561.0)), ks0);
          acc = f2fma(pk((float)(-25360.0 / 2187.0)), ks1, acc);
          acc = f2fma(pk((float)(64448.0 / 6561.0)), ks2, acc);
          acc = f2fma(pk((float)(-212.0 / 729.0)), ks3, acc);
          xs = f2fma(pk(dt), acc, y);
          break;
        case 4:
          ks4 = kacc;
          acc = f2mul(pk((float)(9017.0 / 3168.0)), ks0);
          acc = f2fma(pk((float)(-355.0 / 33.0)), ks1, acc);
          acc = f2fma(pk((float)(46732.0 / 5247.0)), ks2, acc);
          acc = f2fma(pk((float)(49.0 / 176.0)), ks3, acc);
          acc = f2fma(pk((float)(-5103.0 / 18656.0)), ks4, acc);
          xs = f2fma(pk(dt), acc, y);
          break;
        default:
          acc = f2mul(pk((float)(35.0 / 384.0)), ks0);
          acc = f2fma(pk((float)(500.0 / 1113.0)), ks2, acc);
          acc = f2fma(pk((float)(125.0 / 192.0)), ks3, acc);
          acc = f2fma(pk((float)(-2187.0 / 6784.0)), ks4, acc);
          acc = f2fma(pk((float)(11.0 / 84.0)), kacc, acc);
          y = f2fma(pk(dt), acc, y);
          xs = y;
          break;
      }
      sm[oXs + myg * 256 + c]       = lo32(xs);
      sm[oXs + myg * 256 + 128 + c] = hi32(xs);
    }

    __syncthreads();                  // xs(g) + prev fold(g^1) done before G1 reuses sHP
    gemm_h(w1p, sm + oXs + g * 256, sm + oHP, kq, cq);
    __syncthreads();

    // ---- tanh + trace (my group only) ----
    if (mine) {
      const float tcur = ((float)(idx / 6) + cCC[stage]) * dt;
      const float coef = dt * cBWv[stage];
      const float bias = fmaf(tcur, u1r, b1r);
      float h0 = (sm[oHP + c]       + sm[oHP + 256 + c]) +
                 (sm[oHP + 512 + c] + sm[oHP + 768 + c]) + bias;
      float h1 = (sm[oHP + 128 + c]       + sm[oHP + 256 + 128 + c]) +
                 (sm[oHP + 512 + 128 + c] + sm[oHP + 768 + 128 + c]) + bias;
      float a0 = ftanh(h0), a1 = ftanh(h1);
      sm[oA + c]       = a0;
      sm[oA + 128 + c] = a1;
      acc_tr = f2fma(mk2((1.f - a0 * a0) * mr, (1.f - a1 * a1) * mr), pk(coef), acc_tr);
    }
    __syncthreads();
    gemm_h(w2p, sm + oA, sm + oHP, kq, cq);
    __syncthreads();

    // ---- fold + bulk-push (my group only); overlaps other group's wait ----
    if (mine) {
      const int p = idx & 1;
      float v0 = (sm[oHP + c]       + sm[oHP + 256 + c]) +
                 (sm[oHP + 512 + c] + sm[oHP + 768 + c]);
      float v1 = (sm[oHP + 128 + c]       + sm[oHP + 256 + 128 + c]) +
                 (sm[oHP + 512 + 128 + c] + sm[oHP + 768 + 128 + c]);
      ((ull*)(sm + oStg + myg * 512 + (p << 8)))[c] = mk2(v0, v1);
      __syncwarp();
      if (lane == 0) {
        asm volatile("fence.proxy.async.shared::cta;" ::: "memory");
        const uint32_t src = stg0 + ((uint32_t)p << 10);
        const uint32_t dof = (uint32_t)p << 12;
        const uint32_t mof = (uint32_t)p << 3;
        bulk_copy256(dstb[0] + dof, src, rmb[0] + mof);
        bulk_copy256(dstb[1] + dof, src, rmb[1] + mof);
        bulk_copy256(dstb[2] + dof, src, rmb[2] + mof);
        bulk_copy256(dstb[3] + dof, src, rmb[3] + mof);
      }
    }
  }

  // ---- tail: final wait + y update for each group (pstage = 5, p = 1) ----
  {
    const uint32_t lmb = mybmb + 8;
    waitp(lmb, php1);
    const float* pb = sm + oPb + myg * 2048 + 1024;
    const int e2g = c << 1;
    ull kacc = f2add(f2add(*(const ull*)(pb + e2g),       *(const ull*)(pb + 256 + e2g)),
                     f2add(*(const ull*)(pb + 512 + e2g), *(const ull*)(pb + 768 + e2g)));
    kacc = f2add(kacc, b2p);
    acc_dot = f2fma(f2mul(xs, kacc), pk(dt * cBWv[5]), acc_dot);
    ull acc = f2mul(pk((float)(35.0 / 384.0)), ks0);
    acc = f2fma(pk((float)(500.0 / 1113.0)), ks2, acc);
    acc = f2fma(pk((float)(125.0 / 192.0)), ks3, acc);
    acc = f2fma(pk((float)(-2187.0 / 6784.0)), ks4, acc);
    acc = f2fma(pk((float)(11.0 / 84.0)), kacc, acc);
    y = f2fma(pk(dt), acc, y);
  }

  // ---- outputs: z ----
  out[(sb + 2 * myg) * 128 + c]     = lo32(y);
  out[(sb + 2 * myg + 1) * 128 + c] = hi32(y);

  // ---- final reductions: trace (cross-CTA) and dot (local) ----
  {
    float tlo = wsum(lo32(acc_tr)), thi = wsum(hi32(acc_tr));
    float dlo = wsum(lo32(acc_dot)), dhi = wsum(hi32(acc_dot));
    if (lane == 0) {
      sm[oScr + w * 4 + 0] = tlo; sm[oScr + w * 4 + 1] = thi;
      sm[oScr + w * 4 + 2] = dlo; sm[oScr + w * 4 + 3] = dhi;
    }
  }
  __syncthreads();
  if (t < 4) {
    const int gg = t >> 1, sp = t & 1;
    float T = 0.f, D = 0.f;
#pragma unroll
    for (int q = 0; q < 4; ++q) {
      T += sm[oScr + (4 * gg + q) * 4 + sp];
      D += sm[oScr + (4 * gg + q) * 4 + 2 + sp];
    }
    sm[oTx + t] = T;
    sm[oScr + t] = D;  // reuse scratch (post-sync)
  }
  csync();
  if (t < 4) {
    const uint32_t ta = smem_u32(&sm[oTx + t]);
    float T4 = 0.f;
#pragma unroll
    for (uint32_t r = 0; r < 4; ++r) T4 += ldcf(ta, r);
    out[B * 128 + sb + t]     = sm[oLp + t] - T4;       // log_px
    out[B * 128 + B + sb + t] = sm[oScr + t] - T4;      // kl
  }
  csync();  // keep smem alive until peers finish remote reads
}

extern "C" void kernel_launch(void* const* d_in, const int* in_sizes, int n_in,
                              void* d_out, int out_size) {
  const float* x0 = (const float*)d_in[0];
  const float* W1 = (const float*)d_in[1];
  const float* b1 = (const float*)d_in[2];
  const float* u1 = (const float*)d_in[3];
  const float* W2 = (const float*)d_in[4];
  const float* b2 = (const float*)d_in[5];
  const int*   ns = (const int*)d_in[6];
  float* out = (float*)d_out;
  int B = in_sizes[0] / 128;
  vino_kernel<<<B, 256>>>(x0, W1, b1, u1, W2, b2, ns, out, B);
}

// round 9
// speedup vs baseline: 1.0485x; 1.0485x over previous
#include <cuda_runtime.h>
#include <cstdint>

typedef unsigned long long ull;

__constant__ float cCC[6]  = {0.f, 0.2f, 0.3f, 0.8f, (float)(8.0/9.0), 1.0f};
__constant__ float cBWv[6] = {(float)(35.0/384.0), 0.f, (float)(500.0/1113.0),
                              (float)(125.0/192.0), (float)(-2187.0/6784.0),
                              (float)(11.0/84.0)};

// ---- smem layout (float offsets) ----
#define oXs  0        /* 512: per-sample rows [s][128] */
#define oA   512      /* 512 */
#define oHP  1024     /* 4096: [kq:8][s:4][128] GEMM partials */
#define oPb  5120     /* 4096: exchange [p:2][rank:4][pr:2][c:128] ull */
#define oStg 9216     /* 1024: staging [p:2][pr:2][c:128] ull */
#define oScr 10240    /* 32 */
#define oTx  10272    /* 4 */
#define oLp  10276    /* 4 */
#define SMF  10280

__device__ __forceinline__ ull pk(float w) {
  ull r; asm("mov.b64 %0, {%1, %2};" : "=l"(r) : "f"(w), "f"(w)); return r;
}
__device__ __forceinline__ ull mk2(float a, float b) {
  ull r; asm("mov.b64 %0, {%1, %2};" : "=l"(r) : "f"(a), "f"(b)); return r;
}
__device__ __forceinline__ float lo32(ull v) { return __uint_as_float((unsigned)v); }
__device__ __forceinline__ float hi32(ull v) { return __uint_as_float((unsigned)(v >> 32)); }
__device__ __forceinline__ ull f2fma(ull a, ull b, ull c) {
  ull d; asm("fma.rn.f32x2 %0,%1,%2,%3;" : "=l"(d) : "l"(a), "l"(b), "l"(c)); return d;
}
__device__ __forceinline__ ull f2add(ull a, ull b) {
  ull d; asm("add.rn.f32x2 %0,%1,%2;" : "=l"(d) : "l"(a), "l"(b)); return d;
}
__device__ __forceinline__ ull f2mul(ull a, ull b) {
  ull d; asm("mul.rn.f32x2 %0,%1,%2;" : "=l"(d) : "l"(a), "l"(b)); return d;
}
__device__ __forceinline__ float wsum(float v) {
#pragma unroll
  for (int o = 16; o > 0; o >>= 1) v += __shfl_xor_sync(0xffffffffu, v, o);
  return v;
}
__device__ __forceinline__ uint32_t smem_u32(const void* p) {
  uint32_t a;
  asm("{.reg .u64 t; cvta.to.shared.u64 t, %1; cvt.u32.u64 %0, t;}" : "=r"(a) : "l"(p));
  return a;
}
__device__ __forceinline__ uint32_t mapa_u32(uint32_t addr, uint32_t rank) {
  uint32_t ra; asm("mapa.shared::cluster.u32 %0, %1, %2;" : "=r"(ra) : "r"(addr), "r"(rank));
  return ra;
}
__device__ __forceinline__ float ldcf(uint32_t addr, uint32_t rank) {
  uint32_t ra = mapa_u32(addr, rank);
  float v; asm volatile("ld.shared::cluster.f32 %0, [%1];" : "=f"(v) : "r"(ra)); return v;
}
__device__ __forceinline__ void csync() {
  asm volatile("barrier.cluster.arrive.aligned;" ::: "memory");
  asm volatile("barrier.cluster.wait.aligned;" ::: "memory");
}
__device__ __forceinline__ void mbar_init(uint32_t mb, unsigned cnt) {
  asm volatile("mbarrier.init.shared::cta.b64 [%0], %1;" :: "r"(mb), "r"(cnt) : "memory");
}
__device__ __forceinline__ void mbar_arm(uint32_t mb, unsigned tx) {
  asm volatile("mbarrier.arrive.expect_tx.shared::cta.b64 _, [%0], %1;"
               :: "r"(mb), "r"(tx) : "memory");
}
__device__ __forceinline__ void bulk_copy256(uint32_t dst_cluster, uint32_t src_cta,
                                             uint32_t rmb_cluster) {
  asm volatile(
      "cp.async.bulk.shared::cluster.shared::cta.mbarrier::complete_tx::bytes "
      "[%0], [%1], 256, [%2];"
      :: "r"(dst_cluster), "r"(src_cta), "r"(rmb_cluster) : "memory");
}
__device__ __forceinline__ void waitp(uint32_t mb, unsigned ph) {
  unsigned done;
  asm volatile(
      "{\n\t.reg .pred p;\n\t"
      "mbarrier.try_wait.parity.acquire.cluster.shared::cta.b64 p, [%1], %2;\n\t"
      "selp.u32 %0,1,0,p;\n\t}"
      : "=r"(done) : "r"(mb), "r"(ph) : "memory");
  while (!done) {
    asm volatile(
        "{\n\t.reg .pred p;\n\t"
        "mbarrier.try_wait.parity.acquire.cluster.shared::cta.b64 p, [%1], %2, 0x989680;\n\t"
        "selp.u32 %0,1,0,p;\n\t}"
        : "=r"(done) : "r"(mb), "r"(ph) : "memory");
  }
}
__device__ __forceinline__ float ftanh(float x) {
  float e = __expf(2.f * x);
  return 1.f - __fdividef(2.f, e + 1.f);
}

// GEMM tile: thread (cg = t&31, kq = t>>5) computes output cols 4cg..4cg+3 for
// 4 samples over k in [16kq, 16kq+16). Weights k-pair packed: w[j][i] =
// (w_{k0}, w_{k0+1}) for col 4cg+j, k0 = 16kq+2i. x reads are warp-broadcast
// (address depends only on kq = warp id). dst: [kq:8][s:4][128].
__device__ __forceinline__ void gemm_t(const ull (&w)[4][8],
                                       const float* __restrict__ src,
                                       float* __restrict__ dst, int kq, int cg) {
  const float* sp = src + (kq << 4);
  float* dp = dst + (kq << 9) + (cg << 2);
#pragma unroll
  for (int s = 0; s < 4; ++s) {
    ulonglong2 xa = *(const ulonglong2*)(sp + s * 128);       // k 0..3
    ulonglong2 xb = *(const ulonglong2*)(sp + s * 128 + 4);   // k 4..7
    ulonglong2 xc = *(const ulonglong2*)(sp + s * 128 + 8);   // k 8..11
    ulonglong2 xd = *(const ulonglong2*)(sp + s * 128 + 12);  // k 12..15
    ull a0 = f2mul(w[0][0], xa.x), a1 = f2mul(w[1][0], xa.x);
    ull a2 = f2mul(w[2][0], xa.x), a3 = f2mul(w[3][0], xa.x);
    a0 = f2fma(w[0][1], xa.y, a0); a1 = f2fma(w[1][1], xa.y, a1);
    a2 = f2fma(w[2][1], xa.y, a2); a3 = f2fma(w[3][1], xa.y, a3);
    a0 = f2fma(w[0][2], xb.x, a0); a1 = f2fma(w[1][2], xb.x, a1);
    a2 = f2fma(w[2][2], xb.x, a2); a3 = f2fma(w[3][2], xb.x, a3);
    a0 = f2fma(w[0][3], xb.y, a0); a1 = f2fma(w[1][3], xb.y, a1);
    a2 = f2fma(w[2][3], xb.y, a2); a3 = f2fma(w[3][3], xb.y, a3);
    a0 = f2fma(w[0][4], xc.x, a0); a1 = f2fma(w[1][4], xc.x, a1);
    a2 = f2fma(w[2][4], xc.x, a2); a3 = f2fma(w[3][4], xc.x, a3);
    a0 = f2fma(w[0][5], xc.y, a0); a1 = f2fma(w[1][5], xc.y, a1);
    a2 = f2fma(w[2][5], xc.y, a2); a3 = f2fma(w[3][5], xc.y, a3);
    a0 = f2fma(w[0][6], xd.x, a0); a1 = f2fma(w[1][6], xd.x, a1);
    a2 = f2fma(w[2][6], xd.x, a2); a3 = f2fma(w[3][6], xd.x, a3);
    a0 = f2fma(w[0][7], xd.y, a0); a1 = f2fma(w[1][7], xd.y, a1);
    a2 = f2fma(w[2][7], xd.y, a2); a3 = f2fma(w[3][7], xd.y, a3);
    float4 r;
    r.x = lo32(a0) + hi32(a0);
    r.y = lo32(a1) + hi32(a1);
    r.z = lo32(a2) + hi32(a2);
    r.w = lo32(a3) + hi32(a3);
    *(float4*)(dp + s * 128) = r;
  }
}

__global__ void __launch_bounds__(256, 1) __cluster_dims__(4, 1, 1)
vino_kernel(const float* __restrict__ x0g, const float* __restrict__ W1g,
            const float* __restrict__ b1g, const float* __restrict__ u1g,
            const float* __restrict__ W2g, const float* __restrict__ b2g,
            const int* __restrict__ nsp, float* __restrict__ out, int B) {
  __shared__ __align__(16) float sm[SMF];
  __shared__ __align__(8) unsigned long long smbar[2];
  const int t = threadIdx.x;
  const int w = t >> 5, lane = t & 31;
  const int cg = t & 31, kq = t >> 5;       // GEMM tiling (C=4, K=16)
  const int c = t & 127, pr = t >> 7;       // epilogue: element col c, pair pr
  const int s0i = 2 * pr, s1i = 2 * pr + 1;
  const int e2 = t << 1;                    // pair-slot float offset in exchange
  uint32_t rank; asm("mov.u32 %0, %%cluster_ctarank;" : "=r"(rank));
  const int hbase = (int)rank << 7;
  const int sb = (blockIdx.x >> 2) << 2;

  // ---- persistent k-pair-packed weights: 4 cols x 8 k-pairs per GEMM ----
  ull w1p[4][8], w2p[4][8];
#pragma unroll
  for (int j = 0; j < 4; ++j)
#pragma unroll
    for (int i = 0; i < 8; ++i) {
      const int k0 = (kq << 4) + 2 * i;
      const int col = 4 * cg + j;
      w1p[j][i] = mk2(W1g[k0 * 512 + hbase + col], W1g[(k0 + 1) * 512 + hbase + col]);
      w2p[j][i] = mk2(W2g[(hbase + k0) * 128 + col], W2g[(hbase + k0 + 1) * 128 + col]);
    }

  // ---- per-thread constants ----
  const float b1r = b1g[hbase + c];
  const float u1r = u1g[hbase + c];
  const ull b2p = pk(b2g[c]);
  float mr = 0.f;
#pragma unroll 4
  for (int i = 0; i < 128; ++i)
    mr = fmaf(W1g[i * 512 + hbase + c], W2g[(hbase + c) * 128 + i], mr);

  // ---- state init: y holds (s0, s1) pair for element col c ----
  ull y = mk2(x0g[(sb + s0i) * 128 + c], x0g[(sb + s1i) * 128 + c]);
  ull xs = y;
  sm[oXs + s0i * 128 + c] = lo32(xs);
  sm[oXs + s1i * 128 + c] = hi32(xs);

  // ---- mbarriers + precomputed bulk-copy addresses ----
  const uint32_t mb0 = smem_u32(&smbar[0]);
  if (t == 0) {
    mbar_init(mb0, 1); mbar_init(mb0 + 8, 1);
    mbar_arm(mb0, 8192u); mbar_arm(mb0 + 8, 8192u);  // 4 ranks x 2KB
  }
  const uint32_t stgb = smem_u32(sm + oStg);
  const uint32_t spbb = smem_u32(sm + oPb);
  uint32_t dstb[4], rmb[4];
  {
    const uint32_t doff = spbb + ((uint32_t)rank << 11) + ((uint32_t)w << 8);
#pragma unroll
    for (uint32_t r = 0; r < 4; ++r) {
      dstb[r] = mapa_u32(doff, r);
      rmb[r]  = mapa_u32(mb0, r);
    }
  }

  // ---- log p(x0) ----
  {
    float q0 = lo32(y), q1 = hi32(y);
    float ss0 = wsum(q0 * q0), ss1 = wsum(q1 * q1);
    if (lane == 0) { sm[oScr + w * 2] = ss0; sm[oScr + w * 2 + 1] = ss1; }
  }
  __syncthreads();
  if (t < 4) {
    const int gg = t >> 1, sp = t & 1;
    float ss = 0.f;
#pragma unroll
    for (int q = 0; q < 4; ++q) ss += sm[oScr + ((4 * gg + q) << 1) + sp];
    sm[oLp + t] = -0.5f * ss - 117.6241322501981f;  // 64*log(2*pi)
  }
  csync();  // mbar arming + smem init visible cluster-wide

  const int ns = *nsp;
  const float dt = 1.0f / (float)ns;
  ull ks0 = 0, ks1 = 0, ks2 = 0, ks3 = 0, ks4 = 0;
  float tr0 = 0.f, tr1 = 0.f;
  ull acc_dot = 0;
  unsigned par0 = 0, par1 = 0;

  for (int step = 0; step < ns; ++step) {
    const float tstep = (float)step * dt;
#pragma unroll 1
    for (int stage = 0; stage < 6; ++stage) {
      const float coef = dt * cBWv[stage];
      const float tcur = tstep + cCC[stage] * dt;
      const int p = stage & 1;

      __syncthreads();                       // S_A: oXs visible
      gemm_t(w1p, sm + oXs, sm + oHP, kq, cg);
      __syncthreads();                       // S_B

      // tanh + trace accumulation (element (c, s0/s1))
      {
        const float bias = fmaf(tcur, u1r, b1r);
        float h0 = bias, h1 = bias;
#pragma unroll
        for (int q = 0; q < 8; ++q) {
          h0 += sm[oHP + (q << 9) + s0i * 128 + c];
          h1 += sm[oHP + (q << 9) + s1i * 128 + c];
        }
        float a0 = ftanh(h0), a1 = ftanh(h1);
        sm[oA + s0i * 128 + c] = a0;
        sm[oA + s1i * 128 + c] = a1;
        tr0 = fmaf((1.f - a0 * a0) * mr, coef, tr0);
        tr1 = fmaf((1.f - a1 * a1) * mr, coef, tr1);
      }
      __syncthreads();                       // S_C
      gemm_t(w2p, sm + oA, sm + oHP, kq, cg);
      __syncthreads();                       // S_D

      // fold 8 k-segments into parity staging, warp-local; lane 0 bulk-pushes
      {
        float v0 = 0.f, v1 = 0.f;
#pragma unroll
        for (int q = 0; q < 8; ++q) {
          v0 += sm[oHP + (q << 9) + s0i * 128 + c];
          v1 += sm[oHP + (q << 9) + s1i * 128 + c];
        }
        ((ull*)(sm + oStg))[(p << 8) + pr * 128 + c] = mk2(v0, v1);
        __syncwarp();
        if (lane == 0) {
          asm volatile("fence.proxy.async.shared::cta;" ::: "memory");
          const uint32_t src = stgb + ((uint32_t)p << 11) + ((uint32_t)w << 8);
          const uint32_t dof = (uint32_t)p << 13;   // p * 8192 B
          const uint32_t mof = (uint32_t)p << 3;
          bulk_copy256(dstb[0] + dof, src, rmb[0] + mof);
          bulk_copy256(dstb[1] + dof, src, rmb[1] + mof);
          bulk_copy256(dstb[2] + dof, src, rmb[2] + mof);
          bulk_copy256(dstb[3] + dof, src, rmb[3] + mof);
        }
      }

      // wait for all 8KB of this buffer, re-arm for its next use
      {
        const uint32_t lmb = mb0 + (p << 3);
        unsigned ph = p ? par1 : par0;
        waitp(lmb, ph);
        if (p) par1 ^= 1; else par0 ^= 1;
        if (t == 0) mbar_arm(lmb, 8192u);
      }

      // assemble dxdt, accumulate dot, advance RK state (registers)
      {
        const float* pb = sm + oPb + (p << 11);
        ull kacc = f2add(f2add(*(const ull*)(pb + e2),        *(const ull*)(pb + 512 + e2)),
                         f2add(*(const ull*)(pb + 1024 + e2), *(const ull*)(pb + 1536 + e2)));
        kacc = f2add(kacc, b2p);
        acc_dot = f2fma(f2mul(xs, kacc), pk(coef), acc_dot);
        ull acc;
        switch (stage) {
          case 0:
            ks0 = kacc;
            acc = f2mul(pk(0.2f), ks0);
            xs = f2fma(pk(dt), acc, y);
            break;
          case 1:
            ks1 = kacc;
            acc = f2mul(pk(0.075f), ks0);
            acc = f2fma(pk(0.225f), ks1, acc);
            xs = f2fma(pk(dt), acc, y);
            break;
          case 2:
            ks2 = kacc;
            acc = f2mul(pk((float)(44.0 / 45.0)), ks0);
            acc = f2fma(pk((float)(-56.0 / 15.0)), ks1, acc);
            acc = f2fma(pk((float)(32.0 / 9.0)), ks2, acc);
            xs = f2fma(pk(dt), acc, y);
            break;
          case 3:
            ks3 = kacc;
            acc = f2mul(pk((float)(19372.0 / 6561.0)), ks0);
            acc = f2fma(pk((float)(-25360.0 / 2187.0)), ks1, acc);
            acc = f2fma(pk((float)(64448.0 / 6561.0)), ks2, acc);
            acc = f2fma(pk((float)(-212.0 / 729.0)), ks3, acc);
            xs = f2fma(pk(dt), acc, y);
            break;
          case 4:
            ks4 = kacc;
            acc = f2mul(pk((float)(9017.0 / 3168.0)), ks0);
            acc = f2fma(pk((float)(-355.0 / 33.0)), ks1, acc);
            acc = f2fma(pk((float)(46732.0 / 5247.0)), ks2, acc);
            acc = f2fma(pk((float)(49.0 / 176.0)), ks3, acc);
            acc = f2fma(pk((float)(-5103.0 / 18656.0)), ks4, acc);
            xs = f2fma(pk(dt), acc, y);
            break;
          default:
            acc = f2mul(pk((float)(35.0 / 384.0)), ks0);
            acc = f2fma(pk((float)(500.0 / 1113.0)), ks2, acc);
            acc = f2fma(pk((float)(125.0 / 192.0)), ks3, acc);
            acc = f2fma(pk((float)(-2187.0 / 6784.0)), ks4, acc);
            acc = f2fma(pk((float)(11.0 / 84.0)), kacc, acc);
            y = f2fma(pk(dt), acc, y);
            xs = y;
            break;
        }
        sm[oXs + s0i * 128 + c] = lo32(xs);
        sm[oXs + s1i * 128 + c] = hi32(xs);
      }
    }
  }

  // ---- outputs: z ----
  out[(sb + s0i) * 128 + c] = lo32(y);
  out[(sb + s1i) * 128 + c] = hi32(y);

  // ---- final reductions: trace (cross-CTA) and dot (local) ----
  {
    float tlo = wsum(tr0), thi = wsum(tr1);
    float dlo = wsum(lo32(acc_dot)), dhi = wsum(hi32(acc_dot));
    if (lane == 0) {
      sm[oScr + w * 4 + 0] = tlo; sm[oScr + w * 4 + 1] = thi;
      sm[oScr + w * 4 + 2] = dlo; sm[oScr + w * 4 + 3] = dhi;
    }
  }
  __syncthreads();
  if (t < 4) {
    const int gg = t >> 1, sp = t & 1;
    float T = 0.f, D = 0.f;
#pragma unroll
    for (int q = 0; q < 4; ++q) {
      T += sm[oScr + (4 * gg + q) * 4 + sp];
      D += sm[oScr + (4 * gg + q) * 4 + 2 + sp];
    }
    sm[oTx + t] = T;
    sm[oScr + t] = D;  // reuse scratch (post-sync)
  }
  csync();
  if (t < 4) {
    const uint32_t ta = smem_u32(&sm[oTx + t]);
    float T4 = 0.f;
#pragma unroll
    for (uint32_t r = 0; r < 4; ++r) T4 += ldcf(ta, r);
    out[B * 128 + sb + t]     = sm[oLp + t] - T4;       // log_px
    out[B * 128 + B + sb + t] = sm[oScr + t] - T4;      // kl
  }
  csync();  // keep smem alive until peers finish remote reads
}

extern "C" void kernel_launch(void* const* d_in, const int* in_sizes, int n_in,
                              void* d_out, int out_size) {
  const float* x0 = (const float*)d_in[0];
  const float* W1 = (const float*)d_in[1];
  const float* b1 = (const float*)d_in[2];
  const float* u1 = (const float*)d_in[3];
  const float* W2 = (const float*)d_in[4];
  const float* b2 = (const float*)d_in[5];
  const int*   ns = (const int*)d_in[6];
  float* out = (float*)d_out;
  int B = in_sizes[0] / 128;
  vino_kernel<<<B, 256>>>(x0, W1, b1, u1, W2, b2, ns, out, B);
}